// round 9
// baseline (speedup 1.0000x reference)
#include <cuda_runtime.h>
#include <cuda_bf16.h>
#include <cstdint>

// act_shift = log(1/(1-1e-4) - 1) in double, narrowed (matches numpy path).
#define ACT_SHIFT (-9.210240366976184)
#define LOG2E_D   (1.4426950408889634)

#define MAX_RAYS (1 << 20)
__device__ int g_ray_start[MAX_RAYS + 1];

// Single-instruction MUFU paths.
__device__ __forceinline__ float ex2f(float x) {
    float r; asm("ex2.approx.ftz.f32 %0, %1;" : "=f"(r) : "f"(x)); return r;
}
__device__ __forceinline__ float rsqf(float x) {
    float r; asm("rsqrt.approx.ftz.f32 %0, %1;" : "=f"(r) : "f"(x)); return r;
}

// alpha = 1-(1+y)^{-1/2} = y*(1/2 - 3/8 y + 5/16 y^2 - 35/128 y^3 + 63/256 y^4)
__device__ __forceinline__ float alpha_poly(float y) {
    return y * fmaf(y, fmaf(y, fmaf(y, fmaf(y, 0.24609375f, -0.2734375f),
                                    0.3125f), -0.375f), 0.5f);
}

// ---------------------------------------------------------------------------
// Pass 1: segment starts. 16 elements/thread (4x LDG.128, MLP=4);
// predecessor via shfl (lane 0 loads the single straddling scalar).
// Boundary -> predicated store; empty-ray gaps behind a never-taken branch.
// ---------------------------------------------------------------------------
__global__ void find_starts_kernel(const int* __restrict__ ray_id, int M, int Nrays) {
    int t    = blockIdx.x * blockDim.x + threadIdx.x;
    int lane = threadIdx.x & 31;
    int i0   = t * 16;
    bool active = (i0 < M);

    int c[16];
    #pragma unroll
    for (int j = 0; j < 16; ++j) c[j] = 0;
    if (active) {
        if (i0 + 15 < M) {
            int4 a = *reinterpret_cast<const int4*>(ray_id + i0);
            int4 b = *reinterpret_cast<const int4*>(ray_id + i0 + 4);
            int4 e = *reinterpret_cast<const int4*>(ray_id + i0 + 8);
            int4 f = *reinterpret_cast<const int4*>(ray_id + i0 + 12);
            c[0]=a.x; c[1]=a.y; c[2]=a.z; c[3]=a.w;
            c[4]=b.x; c[5]=b.y; c[6]=b.z; c[7]=b.w;
            c[8]=e.x; c[9]=e.y; c[10]=e.z; c[11]=e.w;
            c[12]=f.x; c[13]=f.y; c[14]=f.z; c[15]=f.w;
        } else {
            int last = ray_id[i0];
            #pragma unroll
            for (int j = 0; j < 16; ++j) {
                if (i0 + j < M) last = ray_id[i0 + j];
                c[j] = last;
            }
        }
    }

    int prev = __shfl_up_sync(0xFFFFFFFFu, c[15], 1);
    if (lane == 0) prev = (i0 == 0) ? -1 : __ldg(ray_id + i0 - 1);
    if (!active) return;

    #pragma unroll
    for (int j = 0; j < 16; ++j) {
        int idx = i0 + j;
        int cur = c[j];
        if (idx < M && cur != prev) {
            if ((unsigned)cur <= (unsigned)Nrays) g_ray_start[cur] = idx;
            if (cur > prev + 1)                       // empty rays: ~never
                for (int r = prev + 1; r < cur; ++r)
                    if (r >= 0 && r <= Nrays) g_ray_start[r] = idx;
        }
        if (idx < M) prev = cur;
    }

    if (M - 1 >= i0 && M - 1 < i0 + 16) {             // tail owner
        int last = c[(M - 1) - i0];
        for (int r = last + 1; r <= Nrays; ++r) g_ray_start[r] = M;
    }
}

// ---------------------------------------------------------------------------
// Pass 2: one warp per ray, 160-element tiles so ~every ray is ONE tile.
//   Part 1: 4 elems/lane (float4) over [abase, abase+128)
//   Part 2: 1 elem/lane (scalar, coalesced) over [abase+128, abase+160)
// Product-domain: y = e^{d+shift}, q = 1+y, T = rsq(prefix product),
// alpha = y*poly(y) (pure FMA). Two MUFU rsq + one 5-shfl scan per section.
// ---------------------------------------------------------------------------
__global__ void __launch_bounds__(256)
ray_scan_kernel(const float* __restrict__ density,
                float* __restrict__ out_w,
                float* __restrict__ out_ainv,
                int Nrays, int M) {
    int warp_id = (int)((blockIdx.x * (unsigned)blockDim.x + threadIdx.x) >> 5);
    int lane    = threadIdx.x & 31;
    if (warp_id >= Nrays) return;

    int start = g_ray_start[warp_id];
    int end   = g_ray_start[warp_id + 1];

    const float l2e  = (float)LOG2E_D;
    const float sl2e = (float)(ACT_SHIFT * LOG2E_D);

    int astart = start & ~3;                          // 4-aligned tile origin
    int lo     = start - astart;                      // 0..3 head pad (lane 0)
    float carry = 1.0f;                               // running product of q

    for (int abase = astart; abase < end; abase += 160) {
        // ---- Part 1: [abase, abase+128), 4/lane vectorized ----
        int i0 = abase + lane * 4;                    // stays 4-aligned (160%4==0)
        int hi = end - i0;                            // j valid iff j < hi

        float d0 = 0.f, d1 = 0.f, d2 = 0.f, d3 = 0.f;
        if (i0 + 3 < M) {
            float4 v4 = *reinterpret_cast<const float4*>(density + i0);
            d0 = v4.x; d1 = v4.y; d2 = v4.z; d3 = v4.w;
        } else {
            if (i0     < M) d0 = density[i0];
            if (i0 + 1 < M) d1 = density[i0 + 1];
            if (i0 + 2 < M) d2 = density[i0 + 2];
            if (i0 + 3 < M) d3 = density[i0 + 3];
        }

        float y0 = (0 < hi) ? ex2f(fmaf(d0, l2e, sl2e)) : 0.0f;
        float y1 = (1 < hi) ? ex2f(fmaf(d1, l2e, sl2e)) : 0.0f;
        float y2 = (2 < hi) ? ex2f(fmaf(d2, l2e, sl2e)) : 0.0f;
        float y3 = (3 < hi) ? ex2f(fmaf(d3, l2e, sl2e)) : 0.0f;

        if (abase == astart && lane == 0) {           // head-alignment pad
            if (lo > 0) y0 = 0.0f;
            if (lo > 1) y1 = 0.0f;
            if (lo > 2) y2 = 0.0f;
        }

        float q0 = 1.0f + y0, q1 = 1.0f + y1, q2 = 1.0f + y2, q3 = 1.0f + y3;
        float P0 = q0;
        float P1 = P0 * q1;
        float P2 = P1 * q2;
        float P3 = P2 * q3;

        float v = P3;                                 // warp product scan
        #pragma unroll
        for (int o = 1; o < 32; o <<= 1) {
            float u = __shfl_up_sync(0xFFFFFFFFu, v, o);
            if (lane >= o) v *= u;
        }
        float ve = __shfl_up_sync(0xFFFFFFFFu, v, 1);
        if (lane == 0) ve = 1.0f;
        float P128 = __shfl_sync(0xFFFFFFFFu, v, 31); // part-1 total

        float T = rsqf(carry * ve);

        float a0 = alpha_poly(y0);
        float a1 = alpha_poly(y1);
        float a2 = alpha_poly(y2);
        float a3 = alpha_poly(y3);

        float w0 = a0 * T;  T = fmaf(-T, a0, T);
        float w1 = a1 * T;  T = fmaf(-T, a1, T);
        float w2 = a2 * T;  T = fmaf(-T, a2, T);
        float w3 = a3 * T;

        if (i0 >= start && i0 + 4 <= end) {           // interior quad (common)
            *reinterpret_cast<float4*>(out_w + i0) = make_float4(w0, w1, w2, w3);
        } else {
            if (i0     >= start && 0 < hi) out_w[i0]     = w0;
            if (i0 + 1 >= start && 1 < hi) out_w[i0 + 1] = w1;
            if (i0 + 2 >= start && 2 < hi) out_w[i0 + 2] = w2;
            if (i0 + 3 >= start && 3 < hi) out_w[i0 + 3] = w3;
        }

        // ---- Part 2: [abase+128, abase+160), 1/lane scalar ----
        int i2 = abase + 128 + lane;                  // i2 > start always
        bool v2ok = (i2 < end);
        float d4 = 0.0f;
        if (v2ok) d4 = density[i2];                   // coalesced 32-wide
        float y4 = v2ok ? ex2f(fmaf(d4, l2e, sl2e)) : 0.0f;
        float q4 = 1.0f + y4;

        float s2 = q4;                                // second warp product scan
        #pragma unroll
        for (int o = 1; o < 32; o <<= 1) {
            float u = __shfl_up_sync(0xFFFFFFFFu, s2, o);
            if (lane >= o) s2 *= u;
        }
        float ve2 = __shfl_up_sync(0xFFFFFFFFu, s2, 1);
        if (lane == 0) ve2 = 1.0f;

        float c2 = carry * P128;                      // product up to abase+128
        float T2 = rsqf(c2 * ve2);
        float w4 = alpha_poly(y4) * T2;
        if (v2ok) out_w[i2] = w4;

        carry = c2 * __shfl_sync(0xFFFFFFFFu, s2, 31);
    }

    if (lane == 0) {
        out_ainv[warp_id] = rsqf(carry);
    }
}

extern "C" void kernel_launch(void* const* d_in, const int* in_sizes, int n_in,
                              void* d_out, int out_size) {
    const float* density = (const float*)d_in[0];
    const int*   ray_id  = (const int*)d_in[1];
    int M = in_sizes[0];
    int Nrays = out_size - M;            // output = [weights(M) | alphainv_last(N)]
    if (Nrays < 0) Nrays = 0;
    if (Nrays > MAX_RAYS) Nrays = MAX_RAYS;

    float* out_w    = (float*)d_out;
    float* out_ainv = (float*)d_out + M;

    {
        int threads = 256;
        int chunks  = (M + 15) / 16;
        int blocks  = (chunks + threads - 1) / threads;
        find_starts_kernel<<<blocks, threads>>>(ray_id, M, Nrays);
    }
    {
        int threads = 256;                       // 8 warps/block -> 8 rays/block
        long long total_threads = (long long)Nrays * 32;
        int blocks = (int)((total_threads + threads - 1) / threads);
        if (blocks > 0)
            ray_scan_kernel<<<blocks, threads>>>(density, out_w, out_ainv, Nrays, M);
    }
}

// round 12
// speedup vs baseline: 1.2594x; 1.2594x over previous
#include <cuda_runtime.h>
#include <cuda_bf16.h>
#include <cstdint>

// act_shift = log(1/(1-1e-4) - 1) in double, narrowed (matches numpy path).
#define ACT_SHIFT (-9.210240366976184)
#define LOG2E_D   (1.4426950408889634)

#define MAX_RAYS (1 << 20)
__device__ int g_ray_start[MAX_RAYS + 1];

// Single-instruction MUFU paths.
__device__ __forceinline__ float ex2f(float x) {
    float r; asm("ex2.approx.ftz.f32 %0, %1;" : "=f"(r) : "f"(x)); return r;
}
__device__ __forceinline__ float rsqf(float x) {
    float r; asm("rsqrt.approx.ftz.f32 %0, %1;" : "=f"(r) : "f"(x)); return r;
}

// alpha = 1-(1+y)^{-1/2} = y*(1/2 - 3/8 y + 5/16 y^2 - 35/128 y^3 + 63/256 y^4)
__device__ __forceinline__ float alpha_poly(float y) {
    return y * fmaf(y, fmaf(y, fmaf(y, fmaf(y, 0.24609375f, -0.2734375f),
                                    0.3125f), -0.375f), 0.5f);
}

// ---------------------------------------------------------------------------
// Pass 1 (round-8 proven shape): 8 elements/thread (2x LDG.128); predecessor
// via shfl (lane 0 loads the single straddling scalar). Boundary ->
// predicated store; empty-ray gaps behind a never-taken branch.
// ---------------------------------------------------------------------------
__global__ void find_starts_kernel(const int* __restrict__ ray_id, int M, int Nrays) {
    int t    = blockIdx.x * blockDim.x + threadIdx.x;
    int lane = threadIdx.x & 31;
    int i0   = t * 8;
    bool active = (i0 < M);

    int c[8];
    #pragma unroll
    for (int j = 0; j < 8; ++j) c[j] = 0;
    if (active) {
        if (i0 + 7 < M) {
            int4 a = *reinterpret_cast<const int4*>(ray_id + i0);
            int4 b = *reinterpret_cast<const int4*>(ray_id + i0 + 4);
            c[0]=a.x; c[1]=a.y; c[2]=a.z; c[3]=a.w;
            c[4]=b.x; c[5]=b.y; c[6]=b.z; c[7]=b.w;
        } else {
            int last = ray_id[i0];
            #pragma unroll
            for (int j = 0; j < 8; ++j) {
                if (i0 + j < M) last = ray_id[i0 + j];
                c[j] = last;
            }
        }
    }

    int prev = __shfl_up_sync(0xFFFFFFFFu, c[7], 1);
    if (lane == 0) prev = (i0 == 0) ? -1 : __ldg(ray_id + i0 - 1);
    if (!active) return;

    #pragma unroll
    for (int j = 0; j < 8; ++j) {
        int idx = i0 + j;
        int cur = c[j];
        if (idx < M && cur != prev) {
            if ((unsigned)cur <= (unsigned)Nrays) g_ray_start[cur] = idx;
            if (cur > prev + 1)                       // empty rays: ~never
                for (int r = prev + 1; r < cur; ++r)
                    if (r >= 0 && r <= Nrays) g_ray_start[r] = idx;
        }
        if (idx < M) prev = cur;
    }

    if (M - 1 >= i0 && M - 1 < i0 + 8) {              // tail owner
        int last = c[(M - 1) - i0];
        for (int r = last + 1; r <= Nrays; ++r) g_ray_start[r] = M;
    }
}

// ---------------------------------------------------------------------------
// Pass 2: one warp per ray, 160-element tiles (~every ray = ONE tile).
//   Part 1: 4 elems/lane (float4) over [abase, abase+128)
//   Part 2: 1 elem/lane (scalar) over [abase+128, abase+160),
//           SKIPPED (warp-uniform branch) when the ray ends inside part 1.
// Product-domain: y = e^{d+shift}, q = 1+y, T = rsq(prefix product),
// alpha = y*poly(y) (pure FMA).
// ---------------------------------------------------------------------------
__global__ void __launch_bounds__(256)
ray_scan_kernel(const float* __restrict__ density,
                float* __restrict__ out_w,
                float* __restrict__ out_ainv,
                int Nrays, int M) {
    int warp_id = (int)((blockIdx.x * (unsigned)blockDim.x + threadIdx.x) >> 5);
    int lane    = threadIdx.x & 31;
    if (warp_id >= Nrays) return;

    int start = g_ray_start[warp_id];
    int end   = g_ray_start[warp_id + 1];

    const float l2e  = (float)LOG2E_D;
    const float sl2e = (float)(ACT_SHIFT * LOG2E_D);

    int astart = start & ~3;                          // 4-aligned tile origin
    int lo     = start - astart;                      // 0..3 head pad (lane 0)
    float carry = 1.0f;                               // running product of q

    for (int abase = astart; abase < end; abase += 160) {
        // ---- Part 1: [abase, abase+128), 4/lane vectorized ----
        int i0 = abase + lane * 4;                    // 4-aligned (160 % 4 == 0)
        int hi = end - i0;                            // j valid iff j < hi

        float d0 = 0.f, d1 = 0.f, d2 = 0.f, d3 = 0.f;
        if (i0 + 3 < M) {
            float4 v4 = *reinterpret_cast<const float4*>(density + i0);
            d0 = v4.x; d1 = v4.y; d2 = v4.z; d3 = v4.w;
        } else {
            if (i0     < M) d0 = density[i0];
            if (i0 + 1 < M) d1 = density[i0 + 1];
            if (i0 + 2 < M) d2 = density[i0 + 2];
            if (i0 + 3 < M) d3 = density[i0 + 3];
        }

        float y0 = (0 < hi) ? ex2f(fmaf(d0, l2e, sl2e)) : 0.0f;
        float y1 = (1 < hi) ? ex2f(fmaf(d1, l2e, sl2e)) : 0.0f;
        float y2 = (2 < hi) ? ex2f(fmaf(d2, l2e, sl2e)) : 0.0f;
        float y3 = (3 < hi) ? ex2f(fmaf(d3, l2e, sl2e)) : 0.0f;

        if (abase == astart && lane == 0) {           // head-alignment pad
            if (lo > 0) y0 = 0.0f;
            if (lo > 1) y1 = 0.0f;
            if (lo > 2) y2 = 0.0f;
        }

        float q0 = 1.0f + y0, q1 = 1.0f + y1, q2 = 1.0f + y2, q3 = 1.0f + y3;
        float P0 = q0;
        float P1 = P0 * q1;
        float P2 = P1 * q2;
        float P3 = P2 * q3;

        float v = P3;                                 // warp product scan
        #pragma unroll
        for (int o = 1; o < 32; o <<= 1) {
            float u = __shfl_up_sync(0xFFFFFFFFu, v, o);
            if (lane >= o) v *= u;
        }
        float ve = __shfl_up_sync(0xFFFFFFFFu, v, 1);
        if (lane == 0) ve = 1.0f;
        float P128 = __shfl_sync(0xFFFFFFFFu, v, 31); // part-1 total

        float T = rsqf(carry * ve);

        float a0 = alpha_poly(y0);
        float a1 = alpha_poly(y1);
        float a2 = alpha_poly(y2);
        float a3 = alpha_poly(y3);

        float w0 = a0 * T;  T = fmaf(-T, a0, T);
        float w1 = a1 * T;  T = fmaf(-T, a1, T);
        float w2 = a2 * T;  T = fmaf(-T, a2, T);
        float w3 = a3 * T;

        if (i0 >= start && i0 + 4 <= end) {           // interior quad (common)
            *reinterpret_cast<float4*>(out_w + i0) = make_float4(w0, w1, w2, w3);
        } else {
            if (i0     >= start && 0 < hi) out_w[i0]     = w0;
            if (i0 + 1 >= start && 1 < hi) out_w[i0 + 1] = w1;
            if (i0 + 2 >= start && 2 < hi) out_w[i0 + 2] = w2;
            if (i0 + 3 >= start && 3 < hi) out_w[i0 + 3] = w3;
        }

        carry *= P128;                                // product up to abase+128

        // ---- Part 2: [abase+128, abase+160) — warp-uniform skip ----
        if (abase + 128 < end) {
            int i2 = abase + 128 + lane;              // i2 > start always
            bool v2ok = (i2 < end);
            float d4 = 0.0f;
            if (v2ok) d4 = density[i2];               // coalesced 32-wide
            float y4 = v2ok ? ex2f(fmaf(d4, l2e, sl2e)) : 0.0f;
            float q4 = 1.0f + y4;

            float s2 = q4;                            // second warp product scan
            #pragma unroll
            for (int o = 1; o < 32; o <<= 1) {
                float u = __shfl_up_sync(0xFFFFFFFFu, s2, o);
                if (lane >= o) s2 *= u;
            }
            float ve2 = __shfl_up_sync(0xFFFFFFFFu, s2, 1);
            if (lane == 0) ve2 = 1.0f;

            float T2 = rsqf(carry * ve2);
            float w4 = alpha_poly(y4) * T2;
            if (v2ok) out_w[i2] = w4;

            carry *= __shfl_sync(0xFFFFFFFFu, s2, 31);
        }
    }

    if (lane == 0) {
        out_ainv[warp_id] = rsqf(carry);
    }
}

extern "C" void kernel_launch(void* const* d_in, const int* in_sizes, int n_in,
                              void* d_out, int out_size) {
    const float* density = (const float*)d_in[0];
    const int*   ray_id  = (const int*)d_in[1];
    int M = in_sizes[0];
    int Nrays = out_size - M;            // output = [weights(M) | alphainv_last(N)]
    if (Nrays < 0) Nrays = 0;
    if (Nrays > MAX_RAYS) Nrays = MAX_RAYS;

    float* out_w    = (float*)d_out;
    float* out_ainv = (float*)d_out + M;

    {
        int threads = 256;
        int chunks  = (M + 7) / 8;
        int blocks  = (chunks + threads - 1) / threads;
        find_starts_kernel<<<blocks, threads>>>(ray_id, M, Nrays);
    }
    {
        int threads = 256;                       // 8 warps/block -> 8 rays/block
        long long total_threads = (long long)Nrays * 32;
        int blocks = (int)((total_threads + threads - 1) / threads);
        if (blocks > 0)
            ray_scan_kernel<<<blocks, threads>>>(density, out_w, out_ainv, Nrays, M);
    }
}